// round 3
// baseline (speedup 1.0000x reference)
#include <cuda_runtime.h>
#include <cstdint>

#define FDIM 128
#define MAX_NODES 100000
#define MAX_EDGES 1600000

// ---------------- scratch (device globals: allocation-free rule) ----------------
__device__ float g_bufA[(size_t)MAX_NODES * FDIM];
__device__ float g_bufB[(size_t)MAX_NODES * FDIM];
__device__ float g_isq[MAX_NODES];
__device__ int   g_cnt[MAX_NODES];
__device__ int   g_cursor[MAX_NODES];
__device__ int   g_rowptr[MAX_NODES + 1];
__device__ int2  g_epack[MAX_EDGES];     // {src, bits(norm)}

// ---------------- CSR build ----------------
__global__ void zero_kernel(int* __restrict__ cnt, int* __restrict__ cur, int n) {
    int i = blockIdx.x * blockDim.x + threadIdx.x;
    if (i < n) { cnt[i] = 0; cur[i] = 0; }
}

__global__ void count_kernel(const int* __restrict__ dst, int* __restrict__ cnt, int E) {
    int e = blockIdx.x * blockDim.x + threadIdx.x;
    if (e < E) atomicAdd(&cnt[dst[e]], 1);
}

__global__ void isq_kernel(const int* __restrict__ cnt, float* __restrict__ isq, int n) {
    int i = blockIdx.x * blockDim.x + threadIdx.x;
    if (i < n) isq[i] = rsqrtf((float)(cnt[i] + 1));  // +1: self loop
}

// single-block exclusive scan over counts -> rowptr
__global__ void scan_kernel(const int* __restrict__ cnt, int* __restrict__ rowptr, int n) {
    __shared__ int sh[1024];
    __shared__ int carry;
    if (threadIdx.x == 0) carry = 0;
    __syncthreads();
    for (int base = 0; base < n; base += 1024) {
        int i = base + threadIdx.x;
        int v = (i < n) ? cnt[i] : 0;
        sh[threadIdx.x] = v;
        __syncthreads();
        for (int off = 1; off < 1024; off <<= 1) {
            int t = (threadIdx.x >= off) ? sh[threadIdx.x - off] : 0;
            __syncthreads();
            sh[threadIdx.x] += t;
            __syncthreads();
        }
        if (i < n) rowptr[i] = carry + sh[threadIdx.x] - v;
        __syncthreads();
        if (threadIdx.x == 1023) carry += sh[1023];
        __syncthreads();
    }
    if (threadIdx.x == 0) rowptr[n] = carry;
}

__global__ void fill_kernel(const int* __restrict__ src, const int* __restrict__ dst,
                            const float* __restrict__ isq, const int* __restrict__ rowptr,
                            int* __restrict__ cur, int2* __restrict__ epack, int E) {
    int e = blockIdx.x * blockDim.x + threadIdx.x;
    if (e >= E) return;
    int s = src[e];
    int d = dst[e];
    int pos = rowptr[d] + atomicAdd(&cur[d], 1);
    float w = isq[s] * isq[d];
    epack[pos] = make_int2(s, __float_as_int(w));
}

// ---------------- aggregation: warp per node, CSR gather (self-loop fused) ---------
__global__ void agg_kernel(const float* __restrict__ t, const int* __restrict__ rowptr,
                           const int2* __restrict__ epack, const float* __restrict__ isq,
                           float* __restrict__ agg, int n) {
    int node = (blockIdx.x * blockDim.x + threadIdx.x) >> 5;
    if (node >= n) return;
    int lane = threadIdx.x & 31;
    int beg = rowptr[node];
    int end = rowptr[node + 1];

    float s = isq[node];
    float c = s * s;
    float4 acc = __ldg((const float4*)(t + (size_t)node * FDIM) + lane);
    acc.x *= c; acc.y *= c; acc.z *= c; acc.w *= c;

    for (int j = beg; j < end; ++j) {
        int2 p = __ldg(&epack[j]);                 // broadcast across warp
        float w = __int_as_float(p.y);
        float4 v = __ldg((const float4*)(t + (size_t)p.x * FDIM) + lane);
        acc.x += w * v.x; acc.y += w * v.y; acc.z += w * v.z; acc.w += w * v.w;
    }
    ((float4*)(agg + (size_t)node * FDIM))[lane] = acc;
}

// ---------------- GEMM: C[M,N_OUT] = prologue(A)[M,128] @ W[128,N_OUT] (+ebias) ----
template <int N_OUT, bool PRELU>
__global__ void gemm_kernel(const float* __restrict__ A, const float* __restrict__ W,
                            const float* __restrict__ pbias, const float* __restrict__ ebias,
                            float* __restrict__ C, int M) {
    constexpr int BM   = 64;
    constexpr int COLT = N_OUT / 4;      // threads along N (each does 4 cols)
    constexpr int ROWT = 256 / COLT;     // threads along M
    constexpr int TM   = BM / ROWT;      // rows per thread
    constexpr int AST  = 132;            // padded A-tile stride

    extern __shared__ float smem[];
    float* As = smem;                    // [BM][AST]
    float* Ws = smem + BM * AST;         // [128][N_OUT] row-major

    int tid  = threadIdx.x;
    int row0 = blockIdx.x * BM;

    for (int i = tid; i < 128 * N_OUT / 4; i += 256)
        ((float4*)Ws)[i] = ((const float4*)W)[i];

    for (int i = tid; i < BM * (FDIM / 4); i += 256) {
        int r  = i >> 5;       // FDIM/4 == 32
        int c4 = i & 31;
        int g  = row0 + r;
        float4 v = make_float4(0.f, 0.f, 0.f, 0.f);
        if (g < M) {
            v = ((const float4*)(A + (size_t)g * FDIM))[c4];
            if (pbias) {
                float4 b = ((const float4*)pbias)[c4];
                v.x += b.x; v.y += b.y; v.z += b.z; v.w += b.w;
            }
            if (PRELU) {
                v.x = fmaxf(v.x, 0.f); v.y = fmaxf(v.y, 0.f);
                v.z = fmaxf(v.z, 0.f); v.w = fmaxf(v.w, 0.f);
            }
        }
        *(float4*)(As + r * AST + c4 * 4) = v;
    }
    __syncthreads();

    int tx = tid % COLT;
    int ty = tid / COLT;

    float acc[TM][4];
#pragma unroll
    for (int r = 0; r < TM; ++r) {
        acc[r][0] = 0.f; acc[r][1] = 0.f; acc[r][2] = 0.f; acc[r][3] = 0.f;
    }

    const float* arow0 = As + (ty * TM) * AST;
    const float* wcol  = Ws + tx * 4;

    for (int k = 0; k < 128; k += 4) {
        float4 b0 = *(const float4*)(wcol + (k + 0) * N_OUT);
        float4 b1 = *(const float4*)(wcol + (k + 1) * N_OUT);
        float4 b2 = *(const float4*)(wcol + (k + 2) * N_OUT);
        float4 b3 = *(const float4*)(wcol + (k + 3) * N_OUT);
#pragma unroll
        for (int r = 0; r < TM; ++r) {
            float4 a = *(const float4*)(arow0 + r * AST + k);
            acc[r][0] += a.x * b0.x; acc[r][1] += a.x * b0.y; acc[r][2] += a.x * b0.z; acc[r][3] += a.x * b0.w;
            acc[r][0] += a.y * b1.x; acc[r][1] += a.y * b1.y; acc[r][2] += a.y * b1.z; acc[r][3] += a.y * b1.w;
            acc[r][0] += a.z * b2.x; acc[r][1] += a.z * b2.y; acc[r][2] += a.z * b2.z; acc[r][3] += a.z * b2.w;
            acc[r][0] += a.w * b3.x; acc[r][1] += a.w * b3.y; acc[r][2] += a.w * b3.z; acc[r][3] += a.w * b3.w;
        }
    }

#pragma unroll
    for (int r = 0; r < TM; ++r) {
        int g = row0 + ty * TM + r;
        if (g < M) {
            float4 o = make_float4(acc[r][0], acc[r][1], acc[r][2], acc[r][3]);
            if (ebias) {
                float4 b = ((const float4*)ebias)[tx];
                o.x += b.x; o.y += b.y; o.z += b.z; o.w += b.w;
            }
            ((float4*)(C + (size_t)g * N_OUT))[tx] = o;
        }
    }
}

// ---------------- launch ----------------
extern "C" void kernel_launch(void* const* d_in, const int* in_sizes, int n_in,
                              void* d_out, int out_size) {
    const float* x   = (const float*)d_in[0];
    const int*   ei  = (const int*)d_in[1];     // int32! (JAX x64 disabled)
    const float* W1  = (const float*)d_in[2];
    const float* b1  = (const float*)d_in[3];
    const float* W2  = (const float*)d_in[4];
    const float* b2  = (const float*)d_in[5];
    const float* W3  = (const float*)d_in[6];
    const float* b3  = (const float*)d_in[7];
    const float* Wo  = (const float*)d_in[8];
    const float* bo  = (const float*)d_in[9];

    int n = in_sizes[0] / FDIM;
    int E = in_sizes[1] / 2;
    const int* src = ei;
    const int* dst = ei + E;

    float *bufA, *bufB, *isq;
    int *cnt, *cur, *rowptr;
    int2* epack;
    cudaGetSymbolAddress((void**)&bufA,   g_bufA);
    cudaGetSymbolAddress((void**)&bufB,   g_bufB);
    cudaGetSymbolAddress((void**)&isq,    g_isq);
    cudaGetSymbolAddress((void**)&cnt,    g_cnt);
    cudaGetSymbolAddress((void**)&cur,    g_cursor);
    cudaGetSymbolAddress((void**)&rowptr, g_rowptr);
    cudaGetSymbolAddress((void**)&epack,  g_epack);

    const int SMEM128 = (64 * 132 + 128 * 128) * 4;  // 99,328 B
    const int SMEM64  = (64 * 132 + 128 * 64) * 4;   // 66,560 B
    cudaFuncSetAttribute(gemm_kernel<128, false>, cudaFuncAttributeMaxDynamicSharedMemorySize, SMEM128);
    cudaFuncSetAttribute(gemm_kernel<128, true>,  cudaFuncAttributeMaxDynamicSharedMemorySize, SMEM128);
    cudaFuncSetAttribute(gemm_kernel<64, false>,  cudaFuncAttributeMaxDynamicSharedMemorySize, SMEM64);

    const int T = 256;
    int nb_nodes = (n + T - 1) / T;
    int nb_edges = (E + T - 1) / T;
    int nb_agg   = (int)(((long long)n * 32 + T - 1) / T);
    int nb_gemm  = (n + 63) / 64;

    // ---- CSR build + normalization ----
    zero_kernel<<<nb_nodes, T>>>(cnt, cur, n);
    count_kernel<<<nb_edges, T>>>(dst, cnt, E);
    isq_kernel<<<nb_nodes, T>>>(cnt, isq, n);
    scan_kernel<<<1, 1024>>>(cnt, rowptr, n);
    fill_kernel<<<nb_edges, T>>>(src, dst, isq, rowptr, cur, epack, E);

    // ---- layer 1 ----
    gemm_kernel<128, false><<<nb_gemm, T, SMEM128>>>(x, W1, nullptr, nullptr, bufA, n);
    agg_kernel<<<nb_agg, T>>>(bufA, rowptr, epack, isq, bufB, n);

    // ---- layer 2 ----
    gemm_kernel<128, true><<<nb_gemm, T, SMEM128>>>(bufB, W2, b1, nullptr, bufA, n);
    agg_kernel<<<nb_agg, T>>>(bufA, rowptr, epack, isq, bufB, n);

    // ---- layer 3 ----
    gemm_kernel<128, true><<<nb_gemm, T, SMEM128>>>(bufB, W3, b2, nullptr, bufA, n);
    agg_kernel<<<nb_agg, T>>>(bufA, rowptr, epack, isq, bufB, n);

    // ---- output ----
    gemm_kernel<64, false><<<nb_gemm, T, SMEM64>>>(bufB, Wo, b3, bo, (float*)d_out, n);
}

// round 4
// speedup vs baseline: 1.1931x; 1.1931x over previous
#include <cuda_runtime.h>
#include <cstdint>

#define FDIM 128
#define MAX_NODES 100000
#define MAX_EDGES 1600000
#define SCAN_B 1024
#define MAX_SCAN_BLOCKS ((MAX_NODES + SCAN_B - 1) / SCAN_B)

// ---------------- scratch (device globals: allocation-free rule) ----------------
__device__ float g_bufA[(size_t)MAX_NODES * FDIM];
__device__ float g_bufB[(size_t)MAX_NODES * FDIM];
__device__ float g_isq[MAX_NODES];
__device__ int   g_cnt[MAX_NODES];
__device__ int   g_lpos[MAX_EDGES];          // per-edge local slot within its dst row
__device__ int   g_rowptr[MAX_NODES + 1];
__device__ int   g_partial[MAX_SCAN_BLOCKS];
__device__ int2  g_epack[MAX_EDGES];         // {src, bits(norm)}

// ---------------- CSR build ----------------
__global__ void zero_kernel(int* __restrict__ cnt, int n) {
    int i = blockIdx.x * blockDim.x + threadIdx.x;
    if (i < n) cnt[i] = 0;
}

// count + capture local position in one atomic
__global__ void count_kernel(const int* __restrict__ dst, int* __restrict__ cnt,
                             int* __restrict__ lpos, int E) {
    int e = blockIdx.x * blockDim.x + threadIdx.x;
    if (e < E) lpos[e] = atomicAdd(&cnt[dst[e]], 1);
}

__global__ void isq_kernel(const int* __restrict__ cnt, float* __restrict__ isq, int n) {
    int i = blockIdx.x * blockDim.x + threadIdx.x;
    if (i < n) isq[i] = rsqrtf((float)(cnt[i] + 1));  // +1: self loop
}

// ---- multi-block exclusive scan: per-block scan + partials ----
__global__ void block_scan_kernel(const int* __restrict__ cnt, int* __restrict__ rowptr,
                                  int* __restrict__ partial, int n) {
    __shared__ int sh[SCAN_B];
    int i = blockIdx.x * SCAN_B + threadIdx.x;
    int v = (i < n) ? cnt[i] : 0;
    sh[threadIdx.x] = v;
    __syncthreads();
#pragma unroll
    for (int off = 1; off < SCAN_B; off <<= 1) {
        int t = (threadIdx.x >= off) ? sh[threadIdx.x - off] : 0;
        __syncthreads();
        sh[threadIdx.x] += t;
        __syncthreads();
    }
    if (i < n) rowptr[i] = sh[threadIdx.x] - v;          // exclusive within block
    if (threadIdx.x == SCAN_B - 1) partial[blockIdx.x] = sh[SCAN_B - 1];
}

// scan the (<=98) block partials in place; single small block
__global__ void partial_scan_kernel(int* __restrict__ partial, int nb) {
    if (threadIdx.x == 0) {
        int run = 0;
        for (int b = 0; b < nb; ++b) {
            int v = partial[b];
            partial[b] = run;
            run += v;
        }
        partial[nb] = run;   // total (nb < MAX_SCAN_BLOCKS slack not needed: see launch)
    }
}

__global__ void add_offsets_kernel(int* __restrict__ rowptr, const int* __restrict__ partial,
                                   int n, int nb) {
    int i = blockIdx.x * blockDim.x + threadIdx.x;
    if (i < n) rowptr[i] += partial[i / SCAN_B];
    if (i == 0) rowptr[n] = partial[nb];                 // total edge count
}

__global__ void fill_kernel(const int* __restrict__ src, const int* __restrict__ dst,
                            const float* __restrict__ isq, const int* __restrict__ rowptr,
                            const int* __restrict__ lpos, int2* __restrict__ epack, int E) {
    int e = blockIdx.x * blockDim.x + threadIdx.x;
    if (e >= E) return;
    int s = src[e];
    int d = dst[e];
    int pos = rowptr[d] + lpos[e];
    float w = isq[s] * isq[d];
    epack[pos] = make_int2(s, __float_as_int(w));
}

// ---------------- aggregation: warp per node, CSR gather (self-loop fused) ---------
__global__ void agg_kernel(const float* __restrict__ t, const int* __restrict__ rowptr,
                           const int2* __restrict__ epack, const float* __restrict__ isq,
                           float* __restrict__ agg, int n) {
    int node = (blockIdx.x * blockDim.x + threadIdx.x) >> 5;
    if (node >= n) return;
    int lane = threadIdx.x & 31;
    int beg = rowptr[node];
    int end = rowptr[node + 1];

    float s = isq[node];
    float c = s * s;
    float4 acc = __ldg((const float4*)(t + (size_t)node * FDIM) + lane);
    acc.x *= c; acc.y *= c; acc.z *= c; acc.w *= c;

    for (int j = beg; j < end; ++j) {
        int2 p = __ldg(&epack[j]);                 // broadcast across warp
        float w = __int_as_float(p.y);
        float4 v = __ldg((const float4*)(t + (size_t)p.x * FDIM) + lane);
        acc.x += w * v.x; acc.y += w * v.y; acc.z += w * v.z; acc.w += w * v.w;
    }
    ((float4*)(agg + (size_t)node * FDIM))[lane] = acc;
}

// ---------------- GEMM: C[M,N_OUT] = prologue(A)[M,128] @ W[128,N_OUT] (+ebias) ----
template <int N_OUT, bool PRELU>
__global__ void gemm_kernel(const float* __restrict__ A, const float* __restrict__ W,
                            const float* __restrict__ pbias, const float* __restrict__ ebias,
                            float* __restrict__ C, int M) {
    constexpr int BM   = 64;
    constexpr int COLT = N_OUT / 4;      // threads along N (each does 4 cols)
    constexpr int ROWT = 256 / COLT;     // threads along M
    constexpr int TM   = BM / ROWT;      // rows per thread
    constexpr int AST  = 132;            // padded A-tile stride

    extern __shared__ float smem[];
    float* As = smem;                    // [BM][AST]
    float* Ws = smem + BM * AST;         // [128][N_OUT] row-major

    int tid  = threadIdx.x;
    int row0 = blockIdx.x * BM;

    for (int i = tid; i < 128 * N_OUT / 4; i += 256)
        ((float4*)Ws)[i] = ((const float4*)W)[i];

    for (int i = tid; i < BM * (FDIM / 4); i += 256) {
        int r  = i >> 5;       // FDIM/4 == 32
        int c4 = i & 31;
        int g  = row0 + r;
        float4 v = make_float4(0.f, 0.f, 0.f, 0.f);
        if (g < M) {
            v = ((const float4*)(A + (size_t)g * FDIM))[c4];
            if (pbias) {
                float4 b = ((const float4*)pbias)[c4];
                v.x += b.x; v.y += b.y; v.z += b.z; v.w += b.w;
            }
            if (PRELU) {
                v.x = fmaxf(v.x, 0.f); v.y = fmaxf(v.y, 0.f);
                v.z = fmaxf(v.z, 0.f); v.w = fmaxf(v.w, 0.f);
            }
        }
        *(float4*)(As + r * AST + c4 * 4) = v;
    }
    __syncthreads();

    int tx = tid % COLT;
    int ty = tid / COLT;

    float acc[TM][4];
#pragma unroll
    for (int r = 0; r < TM; ++r) {
        acc[r][0] = 0.f; acc[r][1] = 0.f; acc[r][2] = 0.f; acc[r][3] = 0.f;
    }

    const float* arow0 = As + (ty * TM) * AST;
    const float* wcol  = Ws + tx * 4;

    for (int k = 0; k < 128; k += 4) {
        float4 b0 = *(const float4*)(wcol + (k + 0) * N_OUT);
        float4 b1 = *(const float4*)(wcol + (k + 1) * N_OUT);
        float4 b2 = *(const float4*)(wcol + (k + 2) * N_OUT);
        float4 b3 = *(const float4*)(wcol + (k + 3) * N_OUT);
#pragma unroll
        for (int r = 0; r < TM; ++r) {
            float4 a = *(const float4*)(arow0 + r * AST + k);
            acc[r][0] += a.x * b0.x; acc[r][1] += a.x * b0.y; acc[r][2] += a.x * b0.z; acc[r][3] += a.x * b0.w;
            acc[r][0] += a.y * b1.x; acc[r][1] += a.y * b1.y; acc[r][2] += a.y * b1.z; acc[r][3] += a.y * b1.w;
            acc[r][0] += a.z * b2.x; acc[r][1] += a.z * b2.y; acc[r][2] += a.z * b2.z; acc[r][3] += a.z * b2.w;
            acc[r][0] += a.w * b3.x; acc[r][1] += a.w * b3.y; acc[r][2] += a.w * b3.z; acc[r][3] += a.w * b3.w;
        }
    }

#pragma unroll
    for (int r = 0; r < TM; ++r) {
        int g = row0 + ty * TM + r;
        if (g < M) {
            float4 o = make_float4(acc[r][0], acc[r][1], acc[r][2], acc[r][3]);
            if (ebias) {
                float4 b = ((const float4*)ebias)[tx];
                o.x += b.x; o.y += b.y; o.z += b.z; o.w += b.w;
            }
            ((float4*)(C + (size_t)g * N_OUT))[tx] = o;
        }
    }
}

// ---------------- launch ----------------
extern "C" void kernel_launch(void* const* d_in, const int* in_sizes, int n_in,
                              void* d_out, int out_size) {
    const float* x   = (const float*)d_in[0];
    const int*   ei  = (const int*)d_in[1];     // int32 (JAX x64 disabled)
    const float* W1  = (const float*)d_in[2];
    const float* b1  = (const float*)d_in[3];
    const float* W2  = (const float*)d_in[4];
    const float* b2  = (const float*)d_in[5];
    const float* W3  = (const float*)d_in[6];
    const float* b3  = (const float*)d_in[7];
    const float* Wo  = (const float*)d_in[8];
    const float* bo  = (const float*)d_in[9];

    int n = in_sizes[0] / FDIM;
    int E = in_sizes[1] / 2;
    const int* src = ei;
    const int* dst = ei + E;

    float *bufA, *bufB, *isq;
    int *cnt, *lpos, *rowptr, *partial;
    int2* epack;
    cudaGetSymbolAddress((void**)&bufA,    g_bufA);
    cudaGetSymbolAddress((void**)&bufB,    g_bufB);
    cudaGetSymbolAddress((void**)&isq,     g_isq);
    cudaGetSymbolAddress((void**)&cnt,     g_cnt);
    cudaGetSymbolAddress((void**)&lpos,    g_lpos);
    cudaGetSymbolAddress((void**)&rowptr,  g_rowptr);
    cudaGetSymbolAddress((void**)&partial, g_partial);
    cudaGetSymbolAddress((void**)&epack,   g_epack);

    const int SMEM128 = (64 * 132 + 128 * 128) * 4;  // 99,328 B
    const int SMEM64  = (64 * 132 + 128 * 64) * 4;   // 66,560 B
    cudaFuncSetAttribute(gemm_kernel<128, false>, cudaFuncAttributeMaxDynamicSharedMemorySize, SMEM128);
    cudaFuncSetAttribute(gemm_kernel<128, true>,  cudaFuncAttributeMaxDynamicSharedMemorySize, SMEM128);
    cudaFuncSetAttribute(gemm_kernel<64, false>,  cudaFuncAttributeMaxDynamicSharedMemorySize, SMEM64);

    const int T = 256;
    int nb_nodes = (n + T - 1) / T;
    int nb_edges = (E + T - 1) / T;
    int nb_agg   = (int)(((long long)n * 32 + T - 1) / T);
    int nb_gemm  = (n + 63) / 64;
    int nb_scan  = (n + SCAN_B - 1) / SCAN_B;        // 98 for n=100000 (< MAX_SCAN_BLOCKS)

    // ---- CSR build + normalization ----
    zero_kernel<<<nb_nodes, T>>>(cnt, n);
    count_kernel<<<nb_edges, T>>>(dst, cnt, lpos, E);
    isq_kernel<<<nb_nodes, T>>>(cnt, isq, n);
    block_scan_kernel<<<nb_scan, SCAN_B>>>(cnt, rowptr, partial, n);
    partial_scan_kernel<<<1, 32>>>(partial, nb_scan);
    add_offsets_kernel<<<nb_nodes, T>>>(rowptr, partial, n, nb_scan);
    fill_kernel<<<nb_edges, T>>>(src, dst, isq, rowptr, lpos, epack, E);

    // ---- layer 1 ----
    gemm_kernel<128, false><<<nb_gemm, T, SMEM128>>>(x, W1, nullptr, nullptr, bufA, n);
    agg_kernel<<<nb_agg, T>>>(bufA, rowptr, epack, isq, bufB, n);

    // ---- layer 2 ----
    gemm_kernel<128, true><<<nb_gemm, T, SMEM128>>>(bufB, W2, b1, nullptr, bufA, n);
    agg_kernel<<<nb_agg, T>>>(bufA, rowptr, epack, isq, bufB, n);

    // ---- layer 3 ----
    gemm_kernel<128, true><<<nb_gemm, T, SMEM128>>>(bufB, W3, b2, nullptr, bufA, n);
    agg_kernel<<<nb_agg, T>>>(bufA, rowptr, epack, isq, bufB, n);

    // ---- output ----
    gemm_kernel<64, false><<<nb_gemm, T, SMEM64>>>(bufB, Wo, b3, bo, (float*)d_out, n);
}

// round 6
// speedup vs baseline: 1.2857x; 1.0776x over previous
#include <cuda_runtime.h>
#include <cstdint>

#define FDIM 128
#define MAX_NODES 100000
#define MAX_EDGES 1600000
#define SCAN_B 1024
#define MAX_SCAN_BLOCKS ((MAX_NODES + SCAN_B - 1) / SCAN_B)

// ---------------- scratch (device globals: allocation-free rule) ----------------
__device__ float g_bufA[(size_t)MAX_NODES * FDIM];
__device__ float g_bufB[(size_t)MAX_NODES * FDIM];
__device__ float g_isq[MAX_NODES];
__device__ int   g_cnt[MAX_NODES];
__device__ int   g_lpos[MAX_EDGES];
__device__ int   g_rowptr[MAX_NODES + 1];
__device__ int   g_partial[MAX_SCAN_BLOCKS];
__device__ int2  g_epack[MAX_EDGES];

// ---------------- CSR build ----------------
__global__ void zero_kernel(int* __restrict__ cnt, int n) {
    int i = blockIdx.x * blockDim.x + threadIdx.x;
    if (i < n) cnt[i] = 0;
}
__global__ void count_kernel(const int* __restrict__ dst, int* __restrict__ cnt,
                             int* __restrict__ lpos, int E) {
    int e = blockIdx.x * blockDim.x + threadIdx.x;
    if (e < E) lpos[e] = atomicAdd(&cnt[dst[e]], 1);
}
__global__ void isq_kernel(const int* __restrict__ cnt, float* __restrict__ isq, int n) {
    int i = blockIdx.x * blockDim.x + threadIdx.x;
    if (i < n) isq[i] = rsqrtf((float)(cnt[i] + 1));
}
__global__ void block_scan_kernel(const int* __restrict__ cnt, int* __restrict__ rowptr,
                                  int* __restrict__ partial, int n) {
    __shared__ int sh[SCAN_B];
    int i = blockIdx.x * SCAN_B + threadIdx.x;
    int v = (i < n) ? cnt[i] : 0;
    sh[threadIdx.x] = v;
    __syncthreads();
#pragma unroll
    for (int off = 1; off < SCAN_B; off <<= 1) {
        int t = (threadIdx.x >= off) ? sh[threadIdx.x - off] : 0;
        __syncthreads();
        sh[threadIdx.x] += t;
        __syncthreads();
    }
    if (i < n) rowptr[i] = sh[threadIdx.x] - v;
    if (threadIdx.x == SCAN_B - 1) partial[blockIdx.x] = sh[SCAN_B - 1];
}
__global__ void partial_scan_kernel(int* __restrict__ partial, int nb) {
    if (threadIdx.x == 0) {
        int run = 0;
        for (int b = 0; b < nb; ++b) { int v = partial[b]; partial[b] = run; run += v; }
        partial[nb] = run;
    }
}
__global__ void add_offsets_kernel(int* __restrict__ rowptr, const int* __restrict__ partial,
                                   int n, int nb) {
    int i = blockIdx.x * blockDim.x + threadIdx.x;
    if (i < n) rowptr[i] += partial[i / SCAN_B];
    if (i == 0) rowptr[n] = partial[nb];
}
__global__ void fill_kernel(const int* __restrict__ src, const int* __restrict__ dst,
                            const float* __restrict__ isq, const int* __restrict__ rowptr,
                            const int* __restrict__ lpos, int2* __restrict__ epack, int E) {
    int e = blockIdx.x * blockDim.x + threadIdx.x;
    if (e >= E) return;
    int s = src[e], d = dst[e];
    epack[rowptr[d] + lpos[e]] = make_int2(s, __float_as_int(isq[s] * isq[d]));
}

// ---------------- aggregation: warp per node, CSR gather ----------------
__global__ void agg_kernel(const float* __restrict__ t, const int* __restrict__ rowptr,
                           const int2* __restrict__ epack, const float* __restrict__ isq,
                           float* __restrict__ agg, int n) {
    int node = (blockIdx.x * blockDim.x + threadIdx.x) >> 5;
    if (node >= n) return;
    int lane = threadIdx.x & 31;
    int beg = rowptr[node], end = rowptr[node + 1];
    float s = isq[node], c = s * s;
    float4 acc = __ldg((const float4*)(t + (size_t)node * FDIM) + lane);
    acc.x *= c; acc.y *= c; acc.z *= c; acc.w *= c;
    for (int j = beg; j < end; ++j) {
        int2 p = __ldg(&epack[j]);
        float w = __int_as_float(p.y);
        float4 v = __ldg((const float4*)(t + (size_t)p.x * FDIM) + lane);
        acc.x += w * v.x; acc.y += w * v.y; acc.z += w * v.z; acc.w += w * v.w;
    }
    ((float4*)(agg + (size_t)node * FDIM))[lane] = acc;
}

// ---------------- tf32 helpers ----------------
__device__ __forceinline__ uint32_t f2tf32(float v) {
    uint32_t u;
    asm("cvt.rna.tf32.f32 %0, %1;" : "=r"(u) : "f"(v));
    return u;
}
__device__ __forceinline__ void mma_16n8k8(float& c0, float& c1, float& c2, float& c3,
                                           uint32_t a0, uint32_t a1, uint32_t a2, uint32_t a3,
                                           uint32_t b0, uint32_t b1) {
    asm volatile(
        "mma.sync.aligned.m16n8k8.row.col.f32.tf32.tf32.f32 "
        "{%0,%1,%2,%3}, {%4,%5,%6,%7}, {%8,%9}, {%0,%1,%2,%3};"
        : "+f"(c0), "+f"(c1), "+f"(c2), "+f"(c3)
        : "r"(a0), "r"(a1), "r"(a2), "r"(a3), "r"(b0), "r"(b1));
}

// ---------------- tensor-core GEMM via mma.sync tf32 ------------------------------
// C[M,N_OUT] = prologue(A)[M,128] @ W[128,N_OUT] (+ebias)
// prologue = PRELU ? relu(A + pbias) : (A + pbias); pbias may be null.
// Block: 256 thr = 8 warps; BM = 128 rows (16 per warp); K = 128.
template <int N_OUT, bool PRELU>
__global__ __launch_bounds__(256, 1)
void gemm_mma_kernel(const float* __restrict__ A, const float* __restrict__ W,
                     const float* __restrict__ pbias, const float* __restrict__ ebias,
                     float* __restrict__ C, int M) {
    constexpr int AST = 136;                 // A stride: 136 % 32 == 8 (conflict control)
    constexpr int NS  = (N_OUT == 128) ? 136 : 72;  // W stride: % 32 == 8 -> B frags conflict-free
    constexpr int NT  = N_OUT / 8;           // n-tiles per warp

    extern __shared__ float smem[];
    float* As = smem;                        // [128][AST] tf32-rounded
    float* Ws = smem + 128 * AST;            // [128][NS]  tf32-rounded

    int tid  = threadIdx.x;
    int wid  = tid >> 5;
    int lane = tid & 31;
    int g    = lane >> 2;                    // 0..7
    int tid4 = lane & 3;                     // 0..3
    int row0 = blockIdx.x * 128;

    // ---- stage W (tf32-rounded) ----
    for (int i = tid; i < 128 * (N_OUT / 4); i += 256) {
        int k  = i / (N_OUT / 4);
        int c4 = i % (N_OUT / 4);
        float4 v = ((const float4*)(W + (size_t)k * N_OUT))[c4];
        float* p = Ws + k * NS + c4 * 4;
        p[0] = __uint_as_float(f2tf32(v.x));
        p[1] = __uint_as_float(f2tf32(v.y));
        p[2] = __uint_as_float(f2tf32(v.z));
        p[3] = __uint_as_float(f2tf32(v.w));
    }
    // ---- stage A tile with fused prologue (tf32-rounded) ----
    for (int i = tid; i < 128 * 32; i += 256) {
        int r  = i >> 5;
        int c4 = i & 31;
        int gr = row0 + r;
        float4 v = make_float4(0.f, 0.f, 0.f, 0.f);
        if (gr < M) {
            v = ((const float4*)(A + (size_t)gr * FDIM))[c4];
            if (pbias) {
                float4 b = ((const float4*)pbias)[c4];
                v.x += b.x; v.y += b.y; v.z += b.z; v.w += b.w;
            }
            if (PRELU) {
                v.x = fmaxf(v.x, 0.f); v.y = fmaxf(v.y, 0.f);
                v.z = fmaxf(v.z, 0.f); v.w = fmaxf(v.w, 0.f);
            }
        }
        float* p = As + r * AST + c4 * 4;
        p[0] = __uint_as_float(f2tf32(v.x));
        p[1] = __uint_as_float(f2tf32(v.y));
        p[2] = __uint_as_float(f2tf32(v.z));
        p[3] = __uint_as_float(f2tf32(v.w));
    }
    __syncthreads();

    // ---- accumulators: warp covers rows [wid*16, wid*16+16) x all N ----
    float acc[NT][4];
#pragma unroll
    for (int nt = 0; nt < NT; ++nt) {
        acc[nt][0] = 0.f; acc[nt][1] = 0.f; acc[nt][2] = 0.f; acc[nt][3] = 0.f;
    }

    const float* arow = As + (wid * 16) * AST;
    for (int ks = 0; ks < 16; ++ks) {
        int k0 = ks * 8;
        uint32_t a0 = __float_as_uint(arow[(g)     * AST + k0 + tid4]);
        uint32_t a1 = __float_as_uint(arow[(g + 8) * AST + k0 + tid4]);
        uint32_t a2 = __float_as_uint(arow[(g)     * AST + k0 + tid4 + 4]);
        uint32_t a3 = __float_as_uint(arow[(g + 8) * AST + k0 + tid4 + 4]);
        const float* wk0 = Ws + (k0 + tid4) * NS + g;
        const float* wk1 = Ws + (k0 + tid4 + 4) * NS + g;
#pragma unroll
        for (int nt = 0; nt < NT; ++nt) {
            uint32_t b0 = __float_as_uint(wk0[nt * 8]);
            uint32_t b1 = __float_as_uint(wk1[nt * 8]);
            mma_16n8k8(acc[nt][0], acc[nt][1], acc[nt][2], acc[nt][3],
                       a0, a1, a2, a3, b0, b1);
        }
    }

    // ---- epilogue: c0,c1 -> row g; c2,c3 -> row g+8; cols nt*8 + 2*tid4 (+1) ----
    int r_lo = row0 + wid * 16 + g;
    int r_hi = r_lo + 8;
#pragma unroll
    for (int nt = 0; nt < NT; ++nt) {
        int col = nt * 8 + 2 * tid4;
        float e0 = 0.f, e1 = 0.f;
        if (ebias) { e0 = __ldg(&ebias[col]); e1 = __ldg(&ebias[col + 1]); }
        if (r_lo < M) {
            float2 o = make_float2(acc[nt][0] + e0, acc[nt][1] + e1);
            *(float2*)(C + (size_t)r_lo * N_OUT + col) = o;
        }
        if (r_hi < M) {
            float2 o = make_float2(acc[nt][2] + e0, acc[nt][3] + e1);
            *(float2*)(C + (size_t)r_hi * N_OUT + col) = o;
        }
    }
}

// ---------------- launch ----------------
extern "C" void kernel_launch(void* const* d_in, const int* in_sizes, int n_in,
                              void* d_out, int out_size) {
    const float* x   = (const float*)d_in[0];
    const int*   ei  = (const int*)d_in[1];     // int32 (JAX x64 disabled)
    const float* W1  = (const float*)d_in[2];
    const float* b1  = (const float*)d_in[3];
    const float* W2  = (const float*)d_in[4];
    const float* b2  = (const float*)d_in[5];
    const float* W3  = (const float*)d_in[6];
    const float* b3  = (const float*)d_in[7];
    const float* Wo  = (const float*)d_in[8];
    const float* bo  = (const float*)d_in[9];

    int n = in_sizes[0] / FDIM;
    int E = in_sizes[1] / 2;
    const int* src = ei;
    const int* dst = ei + E;

    float *bufA, *bufB, *isq;
    int *cnt, *lpos, *rowptr, *partial;
    int2* epack;
    cudaGetSymbolAddress((void**)&bufA,    g_bufA);
    cudaGetSymbolAddress((void**)&bufB,    g_bufB);
    cudaGetSymbolAddress((void**)&isq,     g_isq);
    cudaGetSymbolAddress((void**)&cnt,     g_cnt);
    cudaGetSymbolAddress((void**)&lpos,    g_lpos);
    cudaGetSymbolAddress((void**)&rowptr,  g_rowptr);
    cudaGetSymbolAddress((void**)&partial, g_partial);
    cudaGetSymbolAddress((void**)&epack,   g_epack);

    const int SMEM128 = (128 * 136 + 128 * 136) * 4;  // 139,264 B
    const int SMEM64  = (128 * 136 + 128 * 72) * 4;   // 106,496 B
    cudaFuncSetAttribute(gemm_mma_kernel<128, false>, cudaFuncAttributeMaxDynamicSharedMemorySize, SMEM128);
    cudaFuncSetAttribute(gemm_mma_kernel<128, true>,  cudaFuncAttributeMaxDynamicSharedMemorySize, SMEM128);
    cudaFuncSetAttribute(gemm_mma_kernel<64, false>,  cudaFuncAttributeMaxDynamicSharedMemorySize, SMEM64);

    const int T = 256;
    int nb_nodes = (n + T - 1) / T;
    int nb_edges = (E + T - 1) / T;
    int nb_agg   = (int)(((long long)n * 32 + T - 1) / T);
    int nb_gemm  = (n + 127) / 128;
    int nb_scan  = (n + SCAN_B - 1) / SCAN_B;

    // ---- CSR build + normalization ----
    zero_kernel<<<nb_nodes, T>>>(cnt, n);
    count_kernel<<<nb_edges, T>>>(dst, cnt, lpos, E);
    isq_kernel<<<nb_nodes, T>>>(cnt, isq, n);
    block_scan_kernel<<<nb_scan, SCAN_B>>>(cnt, rowptr, partial, n);
    partial_scan_kernel<<<1, 32>>>(partial, nb_scan);
    add_offsets_kernel<<<nb_nodes, T>>>(rowptr, partial, n, nb_scan);
    fill_kernel<<<nb_edges, T>>>(src, dst, isq, rowptr, lpos, epack, E);

    // ---- layer 1 ----
    gemm_mma_kernel<128, false><<<nb_gemm, 256, SMEM128>>>(x, W1, nullptr, nullptr, bufA, n);
    agg_kernel<<<nb_agg, T>>>(bufA, rowptr, epack, isq, bufB, n);

    // ---- layer 2 ----
    gemm_mma_kernel<128, true><<<nb_gemm, 256, SMEM128>>>(bufB, W2, b1, nullptr, bufA, n);
    agg_kernel<<<nb_agg, T>>>(bufA, rowptr, epack, isq, bufB, n);

    // ---- layer 3 ----
    gemm_mma_kernel<128, true><<<nb_gemm, 256, SMEM128>>>(bufB, W3, b2, nullptr, bufA, n);
    agg_kernel<<<nb_agg, T>>>(bufA, rowptr, epack, isq, bufB, n);

    // ---- output ----
    gemm_mma_kernel<64, false><<<nb_gemm, 256, SMEM64>>>(bufB, Wo, b3, bo, (float*)d_out, n);
}

// round 7
// speedup vs baseline: 1.4778x; 1.1495x over previous
#include <cuda_runtime.h>
#include <cstdint>

#define FDIM 128
#define MAX_NODES 100000
#define MAX_EDGES 1600000
#define SCAN_B 1024
#define MAX_SCAN_BLOCKS ((MAX_NODES + SCAN_B - 1) / SCAN_B)

// ---------------- scratch (device globals: allocation-free rule) ----------------
__device__ float g_bufA[(size_t)MAX_NODES * FDIM];
__device__ float g_bufB[(size_t)MAX_NODES * FDIM];
__device__ float g_isq[MAX_NODES];
__device__ int   g_cnt[MAX_NODES];
__device__ int   g_lpos[MAX_EDGES];
__device__ int   g_rowptr[MAX_NODES + 1];
__device__ int   g_partial[MAX_SCAN_BLOCKS];
__device__ int2  g_epack[MAX_EDGES];

// ---------------- CSR build ----------------
__global__ void zero_kernel(int* __restrict__ cnt, int n) {
    int i = blockIdx.x * blockDim.x + threadIdx.x;
    if (i < n) cnt[i] = 0;
}
__global__ void count_kernel(const int* __restrict__ dst, int* __restrict__ cnt,
                             int* __restrict__ lpos, int E) {
    int e = blockIdx.x * blockDim.x + threadIdx.x;
    if (e < E) lpos[e] = atomicAdd(&cnt[dst[e]], 1);
}
__global__ void isq_kernel(const int* __restrict__ cnt, float* __restrict__ isq, int n) {
    int i = blockIdx.x * blockDim.x + threadIdx.x;
    if (i < n) isq[i] = rsqrtf((float)(cnt[i] + 1));
}
__global__ void block_scan_kernel(const int* __restrict__ cnt, int* __restrict__ rowptr,
                                  int* __restrict__ partial, int n) {
    __shared__ int sh[SCAN_B];
    int i = blockIdx.x * SCAN_B + threadIdx.x;
    int v = (i < n) ? cnt[i] : 0;
    sh[threadIdx.x] = v;
    __syncthreads();
#pragma unroll
    for (int off = 1; off < SCAN_B; off <<= 1) {
        int t = (threadIdx.x >= off) ? sh[threadIdx.x - off] : 0;
        __syncthreads();
        sh[threadIdx.x] += t;
        __syncthreads();
    }
    if (i < n) rowptr[i] = sh[threadIdx.x] - v;
    if (threadIdx.x == SCAN_B - 1) partial[blockIdx.x] = sh[SCAN_B - 1];
}
__global__ void partial_scan_kernel(int* __restrict__ partial, int nb) {
    if (threadIdx.x == 0) {
        int run = 0;
        for (int b = 0; b < nb; ++b) { int v = partial[b]; partial[b] = run; run += v; }
        partial[nb] = run;
    }
}
__global__ void add_offsets_kernel(int* __restrict__ rowptr, const int* __restrict__ partial,
                                   int n, int nb) {
    int i = blockIdx.x * blockDim.x + threadIdx.x;
    if (i < n) rowptr[i] += partial[i / SCAN_B];
    if (i == 0) rowptr[n] = partial[nb];
}
__global__ void fill_kernel(const int* __restrict__ src, const int* __restrict__ dst,
                            const float* __restrict__ isq, const int* __restrict__ rowptr,
                            const int* __restrict__ lpos, int2* __restrict__ epack, int E) {
    int e = blockIdx.x * blockDim.x + threadIdx.x;
    if (e >= E) return;
    int s = src[e], d = dst[e];
    epack[rowptr[d] + lpos[e]] = make_int2(s, __float_as_int(isq[s] * isq[d]));
}

// ---------------- aggregation: warp per node, CSR gather ----------------
__global__ void agg_kernel(const float* __restrict__ t, const int* __restrict__ rowptr,
                           const int2* __restrict__ epack, const float* __restrict__ isq,
                           float* __restrict__ agg, int n) {
    int node = (blockIdx.x * blockDim.x + threadIdx.x) >> 5;
    if (node >= n) return;
    int lane = threadIdx.x & 31;
    int beg = rowptr[node], end = rowptr[node + 1];
    float s = isq[node], c = s * s;
    float4 acc = __ldg((const float4*)(t + (size_t)node * FDIM) + lane);
    acc.x *= c; acc.y *= c; acc.z *= c; acc.w *= c;
    for (int j = beg; j < end; ++j) {
        int2 p = __ldg(&epack[j]);
        float w = __int_as_float(p.y);
        float4 v = __ldg((const float4*)(t + (size_t)p.x * FDIM) + lane);
        acc.x += w * v.x; acc.y += w * v.y; acc.z += w * v.z; acc.w += w * v.w;
    }
    ((float4*)(agg + (size_t)node * FDIM))[lane] = acc;
}

// ---------------- tf32 helpers ----------------
__device__ __forceinline__ uint32_t f2tf32(float v) {
    uint32_t u;
    asm("cvt.rna.tf32.f32 %0, %1;" : "=r"(u) : "f"(v));
    return u;
}
__device__ __forceinline__ void mma_16n8k8(float& c0, float& c1, float& c2, float& c3,
                                           uint32_t a0, uint32_t a1, uint32_t a2, uint32_t a3,
                                           uint32_t b0, uint32_t b1) {
    asm volatile(
        "mma.sync.aligned.m16n8k8.row.col.f32.tf32.tf32.f32 "
        "{%0,%1,%2,%3}, {%4,%5,%6,%7}, {%8,%9}, {%0,%1,%2,%3};"
        : "+f"(c0), "+f"(c1), "+f"(c2), "+f"(c3)
        : "r"(a0), "r"(a1), "r"(a2), "r"(a3), "r"(b0), "r"(b1));
}

// ---------------- tensor-core GEMM via mma.sync tf32 ------------------------------
// C[M,N_OUT] = prologue(A)[M,128] @ W[128,N_OUT] (+ebias)
// Block: 256 thr = 8 warps laid out ROWG x COLG; warp tile = 16 rows x 64 cols (NT=8).
// N_OUT=128: ROWG=4, COLG=2, BM=64.  N_OUT=64: ROWG=8, COLG=1, BM=128.
// SMEM ~104-107KB -> 2 CTAs/SM (16 warps) for latency hiding.
template <int N_OUT, bool PRELU>
__global__ __launch_bounds__(256, 2)
void gemm_mma_kernel(const float* __restrict__ A, const float* __restrict__ W,
                     const float* __restrict__ pbias, const float* __restrict__ ebias,
                     float* __restrict__ C, int M) {
    constexpr int COLG = N_OUT / 64;
    constexpr int ROWG = 8 / COLG;
    constexpr int BM   = ROWG * 16;
    constexpr int AST  = 136;                       // % 32 == 8
    constexpr int NS   = (N_OUT == 128) ? 136 : 72; // % 32 == 8
    constexpr int NT   = 8;                         // 8 n-tiles of 8 = 64 cols per warp

    extern __shared__ float smem[];
    float* As = smem;                               // [BM][AST] tf32-rounded
    float* Ws = smem + BM * AST;                    // [128][NS] tf32-rounded

    int tid  = threadIdx.x;
    int wid  = tid >> 5;
    int lane = tid & 31;
    int g    = lane >> 2;                           // 0..7
    int tid4 = lane & 3;                            // 0..3
    int wid_r = wid / COLG;                         // row group
    int wid_c = wid % COLG;                         // col group
    int row0 = blockIdx.x * BM;

    // ---- stage W (tf32-rounded) ----
    for (int i = tid; i < 128 * (N_OUT / 4); i += 256) {
        int k  = i / (N_OUT / 4);
        int c4 = i % (N_OUT / 4);
        float4 v = ((const float4*)(W + (size_t)k * N_OUT))[c4];
        float* p = Ws + k * NS + c4 * 4;
        p[0] = __uint_as_float(f2tf32(v.x));
        p[1] = __uint_as_float(f2tf32(v.y));
        p[2] = __uint_as_float(f2tf32(v.z));
        p[3] = __uint_as_float(f2tf32(v.w));
    }
    // ---- stage A tile with fused prologue (tf32-rounded) ----
    for (int i = tid; i < BM * 32; i += 256) {
        int r  = i >> 5;
        int c4 = i & 31;
        int gr = row0 + r;
        float4 v = make_float4(0.f, 0.f, 0.f, 0.f);
        if (gr < M) {
            v = ((const float4*)(A + (size_t)gr * FDIM))[c4];
            if (pbias) {
                float4 b = ((const float4*)pbias)[c4];
                v.x += b.x; v.y += b.y; v.z += b.z; v.w += b.w;
            }
            if (PRELU) {
                v.x = fmaxf(v.x, 0.f); v.y = fmaxf(v.y, 0.f);
                v.z = fmaxf(v.z, 0.f); v.w = fmaxf(v.w, 0.f);
            }
        }
        float* p = As + r * AST + c4 * 4;
        p[0] = __uint_as_float(f2tf32(v.x));
        p[1] = __uint_as_float(f2tf32(v.y));
        p[2] = __uint_as_float(f2tf32(v.z));
        p[3] = __uint_as_float(f2tf32(v.w));
    }
    __syncthreads();

    // ---- accumulators: 16 rows x 64 cols per warp ----
    float acc[NT][4];
#pragma unroll
    for (int nt = 0; nt < NT; ++nt) {
        acc[nt][0] = 0.f; acc[nt][1] = 0.f; acc[nt][2] = 0.f; acc[nt][3] = 0.f;
    }

    const float* arow = As + (wid_r * 16) * AST;
    const int ncol0 = wid_c * 64;
    for (int ks = 0; ks < 16; ++ks) {
        int k0 = ks * 8;
        uint32_t a0 = __float_as_uint(arow[(g)     * AST + k0 + tid4]);
        uint32_t a1 = __float_as_uint(arow[(g + 8) * AST + k0 + tid4]);
        uint32_t a2 = __float_as_uint(arow[(g)     * AST + k0 + tid4 + 4]);
        uint32_t a3 = __float_as_uint(arow[(g + 8) * AST + k0 + tid4 + 4]);
        const float* wk0 = Ws + (k0 + tid4) * NS + ncol0 + g;
        const float* wk1 = Ws + (k0 + tid4 + 4) * NS + ncol0 + g;
#pragma unroll
        for (int nt = 0; nt < NT; ++nt) {
            uint32_t b0 = __float_as_uint(wk0[nt * 8]);
            uint32_t b1 = __float_as_uint(wk1[nt * 8]);
            mma_16n8k8(acc[nt][0], acc[nt][1], acc[nt][2], acc[nt][3],
                       a0, a1, a2, a3, b0, b1);
        }
    }

    // ---- epilogue ----
    int r_lo = row0 + wid_r * 16 + g;
    int r_hi = r_lo + 8;
#pragma unroll
    for (int nt = 0; nt < NT; ++nt) {
        int col = ncol0 + nt * 8 + 2 * tid4;
        float e0 = 0.f, e1 = 0.f;
        if (ebias) { e0 = __ldg(&ebias[col]); e1 = __ldg(&ebias[col + 1]); }
        if (r_lo < M) {
            float2 o = make_float2(acc[nt][0] + e0, acc[nt][1] + e1);
            *(float2*)(C + (size_t)r_lo * N_OUT + col) = o;
        }
        if (r_hi < M) {
            float2 o = make_float2(acc[nt][2] + e0, acc[nt][3] + e1);
            *(float2*)(C + (size_t)r_hi * N_OUT + col) = o;
        }
    }
}

// ---------------- launch ----------------
extern "C" void kernel_launch(void* const* d_in, const int* in_sizes, int n_in,
                              void* d_out, int out_size) {
    const float* x   = (const float*)d_in[0];
    const int*   ei  = (const int*)d_in[1];     // int32 (JAX x64 disabled)
    const float* W1  = (const float*)d_in[2];
    const float* b1  = (const float*)d_in[3];
    const float* W2  = (const float*)d_in[4];
    const float* b2  = (const float*)d_in[5];
    const float* W3  = (const float*)d_in[6];
    const float* b3  = (const float*)d_in[7];
    const float* Wo  = (const float*)d_in[8];
    const float* bo  = (const float*)d_in[9];

    int n = in_sizes[0] / FDIM;
    int E = in_sizes[1] / 2;
    const int* src = ei;
    const int* dst = ei + E;

    float *bufA, *bufB, *isq;
    int *cnt, *lpos, *rowptr, *partial;
    int2* epack;
    cudaGetSymbolAddress((void**)&bufA,    g_bufA);
    cudaGetSymbolAddress((void**)&bufB,    g_bufB);
    cudaGetSymbolAddress((void**)&isq,     g_isq);
    cudaGetSymbolAddress((void**)&cnt,     g_cnt);
    cudaGetSymbolAddress((void**)&lpos,    g_lpos);
    cudaGetSymbolAddress((void**)&rowptr,  g_rowptr);
    cudaGetSymbolAddress((void**)&partial, g_partial);
    cudaGetSymbolAddress((void**)&epack,   g_epack);

    const int SMEM128 = (64 * 136 + 128 * 136) * 4;   // 104,448 B (2 CTAs/SM)
    const int SMEM64  = (128 * 136 + 128 * 72) * 4;   // 106,496 B (2 CTAs/SM)
    cudaFuncSetAttribute(gemm_mma_kernel<128, false>, cudaFuncAttributeMaxDynamicSharedMemorySize, SMEM128);
    cudaFuncSetAttribute(gemm_mma_kernel<128, true>,  cudaFuncAttributeMaxDynamicSharedMemorySize, SMEM128);
    cudaFuncSetAttribute(gemm_mma_kernel<64, false>,  cudaFuncAttributeMaxDynamicSharedMemorySize, SMEM64);

    const int T = 256;
    int nb_nodes  = (n + T - 1) / T;
    int nb_edges  = (E + T - 1) / T;
    int nb_agg    = (int)(((long long)n * 32 + T - 1) / T);
    int nb_gemm128 = (n + 63) / 64;     // BM=64 for N_OUT=128
    int nb_gemm64  = (n + 127) / 128;   // BM=128 for N_OUT=64
    int nb_scan   = (n + SCAN_B - 1) / SCAN_B;

    // ---- CSR build + normalization ----
    zero_kernel<<<nb_nodes, T>>>(cnt, n);
    count_kernel<<<nb_edges, T>>>(dst, cnt, lpos, E);
    isq_kernel<<<nb_nodes, T>>>(cnt, isq, n);
    block_scan_kernel<<<nb_scan, SCAN_B>>>(cnt, rowptr, partial, n);
    partial_scan_kernel<<<1, 32>>>(partial, nb_scan);
    add_offsets_kernel<<<nb_nodes, T>>>(rowptr, partial, n, nb_scan);
    fill_kernel<<<nb_edges, T>>>(src, dst, isq, rowptr, lpos, epack, E);

    // ---- layer 1 ----
    gemm_mma_kernel<128, false><<<nb_gemm128, 256, SMEM128>>>(x, W1, nullptr, nullptr, bufA, n);
    agg_kernel<<<nb_agg, T>>>(bufA, rowptr, epack, isq, bufB, n);

    // ---- layer 2 ----
    gemm_mma_kernel<128, true><<<nb_gemm128, 256, SMEM128>>>(bufB, W2, b1, nullptr, bufA, n);
    agg_kernel<<<nb_agg, T>>>(bufA, rowptr, epack, isq, bufB, n);

    // ---- layer 3 ----
    gemm_mma_kernel<128, true><<<nb_gemm128, 256, SMEM128>>>(bufB, W3, b2, nullptr, bufA, n);
    agg_kernel<<<nb_agg, T>>>(bufA, rowptr, epack, isq, bufB, n);

    // ---- output ----
    gemm_mma_kernel<64, false><<<nb_gemm64, 256, SMEM64>>>(bufB, Wo, b3, bo, (float*)d_out, n);
}